// round 7
// baseline (speedup 1.0000x reference)
#include <cuda_runtime.h>
#include <stdint.h>

// TBE pooled embedding forward — warp-specialized LDG + TMA gather.
// weights: [T, E, D] fp32; indices: [T*B*L] int32; offsets: [T*B+1] int32
// out: [B, T*D] fp32, pooled bag (t, b) -> out[b, t*D : (t+1)*D]
//
// Per block of 8 warps: warps 0-5 gather their bag via LDG.128 (the proven
// 6 TB/s path); warps 6-7 gather theirs via cp.async.bulk G->S (async/TMA
// queue, not counted against the SM-wide outstanding-LDG cap). TMA warp
// stalls don't block LDG warps. smem = 2 slabs x 10KB -> occupancy stays 6
// CTAs/SM. Tests whether the ~6 TB/s plateau is an LDG-request cap (win) or
// the DRAM random-512B service ceiling (neutral).

#define T_TABLES 16
#define E_ROWS   100000
#define D_DIM    128
#define B_BAGS   4096
#define WARPS    8
#define TMA_WARP0 6            // warps 6,7 take the TMA path
#define ROW_BYTES 512
#define SLAB_BYTES (20 * ROW_BYTES)                  // 10240 per TMA warp
#define SMEM_BYTES (128 + 2 * SLAB_BYTES)            // 20608

__device__ __forceinline__ uint32_t smem_u32(const void* p) {
    return (uint32_t)__cvta_generic_to_shared(p);
}

__device__ __forceinline__ float4 ldcg_f4(const float4* p) {
    float4 v;
    asm volatile("ld.global.cg.v4.f32 {%0,%1,%2,%3}, [%4];"
                 : "=f"(v.x), "=f"(v.y), "=f"(v.z), "=f"(v.w) : "l"(p));
    return v;
}

__device__ __forceinline__ void acc_add(float4& a, const float4 v) {
    a.x += v.x; a.y += v.y; a.z += v.z; a.w += v.w;
}

__device__ __forceinline__ void reduce_ragged(
    const float4* __restrict__ tbl, const int* __restrict__ indices,
    int start, int end, int lane, float4& a0, float4& a1, float4& a2, float4& a3)
{
    int j = start;
    const int n4 = start + ((end - start) & ~3);
    #pragma unroll 1
    for (; j < n4; j += 4) {
        const int i0 = __ldg(indices + j + 0);
        const int i1 = __ldg(indices + j + 1);
        const int i2 = __ldg(indices + j + 2);
        const int i3 = __ldg(indices + j + 3);
        acc_add(a0, ldcg_f4(tbl + (size_t)i0 * (D_DIM / 4) + lane));
        acc_add(a1, ldcg_f4(tbl + (size_t)i1 * (D_DIM / 4) + lane));
        acc_add(a2, ldcg_f4(tbl + (size_t)i2 * (D_DIM / 4) + lane));
        acc_add(a3, ldcg_f4(tbl + (size_t)i3 * (D_DIM / 4) + lane));
    }
    for (; j < end; j++) {
        const int i0 = __ldg(indices + j);
        acc_add(a0, ldcg_f4(tbl + (size_t)i0 * (D_DIM / 4) + lane));
    }
}

__global__ __launch_bounds__(WARPS * 32, 6)
void tbe_ws_kernel(const float* __restrict__ weights,
                   const int* __restrict__ indices,
                   const int* __restrict__ offsets,
                   float* __restrict__ out) {
    extern __shared__ char smem[];
    const int wid  = threadIdx.x >> 5;
    const int lane = threadIdx.x & 31;
    const int bag  = blockIdx.x * WARPS + wid;

    const int t = bag / B_BAGS;   // bags are table-major
    const int b = bag % B_BAGS;

    const int start = __ldg(offsets + bag);
    const int end   = __ldg(offsets + bag + 1);
    const int n     = end - start;

    const float4* __restrict__ tbl =
        reinterpret_cast<const float4*>(weights + (size_t)t * E_ROWS * D_DIM);

    float4 a0 = make_float4(0.f, 0.f, 0.f, 0.f);
    float4 a1 = make_float4(0.f, 0.f, 0.f, 0.f);
    float4 a2 = make_float4(0.f, 0.f, 0.f, 0.f);
    float4 a3 = make_float4(0.f, 0.f, 0.f, 0.f);

    if (wid >= TMA_WARP0 && n == 20) {
        // ---- TMA path (warps 6,7): 20 bulk copies, one wait, reduce ----
        const int tw = wid - TMA_WARP0;
        const uint32_t mbar   = smem_u32(smem + tw * 16);
        char* const slab      = smem + 128 + tw * SLAB_BYTES;
        const uint32_t slab_s = smem_u32(slab);

        if (lane == 0) {
            asm volatile("mbarrier.init.shared.b64 [%0], %1;"
                         :: "r"(mbar), "r"(1) : "memory");
        }
        asm volatile("fence.proxy.async.shared::cta;" ::: "memory");
        __syncwarp();

        if (lane == 0) {
            asm volatile("mbarrier.arrive.expect_tx.shared.b64 _, [%0], %1;"
                         :: "r"(mbar), "r"(20 * ROW_BYTES) : "memory");
        }
        __syncwarp();
        if (lane < 20) {
            const int idx = __ldg(indices + start + lane);
            const char* g = reinterpret_cast<const char*>(tbl) + (size_t)idx * ROW_BYTES;
            asm volatile(
                "cp.async.bulk.shared::cluster.global.mbarrier::complete_tx::bytes "
                "[%0], [%1], %2, [%3];"
                :: "r"(slab_s + lane * ROW_BYTES), "l"(g),
                   "r"(ROW_BYTES), "r"(mbar)
                : "memory");
        }

        asm volatile(
            "{\n\t"
            ".reg .pred P;\n\t"
            "WAIT_%=:\n\t"
            "mbarrier.try_wait.parity.acquire.cta.shared::cta.b64 P, [%0], 0, 0x989680;\n\t"
            "@P bra WAIT_DONE_%=;\n\t"
            "bra WAIT_%=;\n\t"
            "WAIT_DONE_%=:\n\t"
            "}"
            :: "r"(mbar) : "memory");

        const float4* rows = reinterpret_cast<const float4*>(slab);
        #pragma unroll
        for (int k = 0; k < 20; k += 4) {
            acc_add(a0, rows[(k + 0) * (ROW_BYTES / 16) + lane]);
            acc_add(a1, rows[(k + 1) * (ROW_BYTES / 16) + lane]);
            acc_add(a2, rows[(k + 2) * (ROW_BYTES / 16) + lane]);
            acc_add(a3, rows[(k + 3) * (ROW_BYTES / 16) + lane]);
        }
    } else if (n == 20 && ((start & 3) == 0)) {
        // ---- LDG fast path (warps 0-5) ----
        const int4* __restrict__ ip = reinterpret_cast<const int4*>(indices + start);
        int idx[20];
        #pragma unroll
        for (int g = 0; g < 5; g++) {
            const int4 q = __ldg(ip + g);
            idx[g * 4 + 0] = q.x;
            idx[g * 4 + 1] = q.y;
            idx[g * 4 + 2] = q.z;
            idx[g * 4 + 3] = q.w;
        }
        float4 v[20];
        #pragma unroll
        for (int k = 0; k < 20; k++)
            v[k] = ldcg_f4(tbl + (size_t)idx[k] * (D_DIM / 4) + lane);
        #pragma unroll
        for (int k = 0; k < 20; k += 4) {
            acc_add(a0, v[k + 0]);
            acc_add(a1, v[k + 1]);
            acc_add(a2, v[k + 2]);
            acc_add(a3, v[k + 3]);
        }
    } else {
        reduce_ragged(tbl, indices, start, end, lane, a0, a1, a2, a3);
    }

    acc_add(a0, a1);
    acc_add(a2, a3);
    acc_add(a0, a2);

    float4* const o =
        reinterpret_cast<float4*>(out + (size_t)b * (T_TABLES * D_DIM) + t * D_DIM);
    o[lane] = a0;
}

extern "C" void kernel_launch(void* const* d_in, const int* in_sizes, int n_in,
                              void* d_out, int out_size) {
    const float* weights = (const float*)d_in[0];
    const int*   indices = (const int*)d_in[1];
    const int*   offsets = (const int*)d_in[2];
    float*       out     = (float*)d_out;

    const int num_bags = T_TABLES * B_BAGS;        // 65536
    const int blocks   = num_bags / WARPS;          // 8192
    tbe_ws_kernel<<<blocks, WARPS * 32, SMEM_BYTES>>>(weights, indices, offsets, out);
}